// round 2
// baseline (speedup 1.0000x reference)
#include <cuda_runtime.h>

// SSIM loss, fully fused single kernel:
//   5 separable 11-tap Gaussian blurs (vertical in register rings, horizontal via smem)
//   + SSIM map + global mean + last-block finalize.
// Gaussian weights are compile-time float literals so ptxas emits FFMA-imm (rt_SMSP=1).

#define IMG_H 1024
#define IMG_W 1024
#define W_OUT 118          // output columns per block
#define EW    128          // extended columns (with 2*5 halo) == blockDim.x
#define ROWS  64           // output rows per block
#define NBLK  (9 * (IMG_H / ROWS) * 16)   // 9*16*16 = 2304

__device__ double g_acc = 0.0;
__device__ unsigned int g_cnt = 0u;

__global__ __launch_bounds__(EW) void ssim_kernel(const float* __restrict__ img1,
                                                  const float* __restrict__ img2,
                                                  float* __restrict__ out) {
    // Gaussian weights (float32 of the numpy pipeline), as literals -> FFMA immediates.
    const float KW[11] = {
        0.0010283853f, 0.0075987626f, 0.0360007730f, 0.1093606900f,
        0.2130055300f, 0.2660117200f, 0.2130055300f, 0.1093606900f,
        0.0360007730f, 0.0075987626f, 0.0010283853f
    };

    const int tid = threadIdx.x;
    const int bx  = blockIdx.x;   // column strips of 118
    const int by  = blockIdx.y;   // row strips of ROWS
    const int bz  = blockIdx.z;   // batch
    const size_t base = (size_t)bz * (size_t)(IMG_H * IMG_W);

    const int xg  = bx * W_OUT - 5 + tid;          // global column this thread loads
    const bool xok = (xg >= 0) && (xg < IMG_W);
    const int y0  = by * ROWS;
    const float* p1 = img1 + base + xg;
    const float* p2 = img2 + base + xg;

    __shared__ float sbuf[11][5][EW];   // one 11-row chunk of 5 vertical-sum fields
    __shared__ float red[4];

    // Register rings: row ri lives in slot (ri - (y0-5)) mod 11.
    float a[11], b[11], aa[11], bb[11], ab[11];
    #pragma unroll
    for (int i = 0; i < 10; ++i) {
        const int ri = y0 - 5 + i;
        const bool ok = xok && (ri >= 0);          // ri < IMG_H guaranteed here
        const float av = ok ? __ldg(p1 + (size_t)ri * IMG_W) : 0.f;
        const float bv = ok ? __ldg(p2 + (size_t)ri * IMG_W) : 0.f;
        a[i] = av; b[i] = bv;
        aa[i] = av * av; bb[i] = bv * bv; ab[i] = av * bv;
    }
    a[10] = b[10] = aa[10] = bb[10] = ab[10] = 0.f;

    float acc = 0.f;
    const bool hok = (tid >= 5) && (tid < 5 + W_OUT) && (xg < IMG_W);

    #pragma unroll 1
    for (int rb = 0; rb < ROWS; rb += 11) {
        // ---- vertical phase: 11 rows of 5 fields into smem ----
        #pragma unroll
        for (int p = 0; p < 11; ++p) {
            const int r = rb + p;
            if (r < ROWS) {
                {   // load new bottom row y0+r+5 into slot (p+10)%11, precompute products
                    const int ri = y0 + r + 5;
                    const bool ok = xok && (ri < IMG_H);
                    const float av = ok ? __ldg(p1 + (size_t)ri * IMG_W) : 0.f;
                    const float bv = ok ? __ldg(p2 + (size_t)ri * IMG_W) : 0.f;
                    const int sl = (p + 10) % 11;
                    a[sl] = av; b[sl] = bv;
                    aa[sl] = av * av; bb[sl] = bv * bv; ab[sl] = av * bv;
                }
                float s1 = 0.f, s2 = 0.f, s3 = 0.f, s4 = 0.f, s5 = 0.f;
                #pragma unroll
                for (int d = 0; d < 11; ++d) {
                    const int sl = (p + d) % 11;       // compile-time
                    s1 = fmaf(KW[d], a[sl],  s1);
                    s2 = fmaf(KW[d], b[sl],  s2);
                    s3 = fmaf(KW[d], aa[sl], s3);
                    s4 = fmaf(KW[d], bb[sl], s4);
                    s5 = fmaf(KW[d], ab[sl], s5);
                }
                sbuf[p][0][tid] = s1;
                sbuf[p][1][tid] = s2;
                sbuf[p][2][tid] = s3;
                sbuf[p][3][tid] = s4;
                sbuf[p][4][tid] = s5;
            }
        }
        __syncthreads();

        // ---- horizontal phase: 11-tap + SSIM for the chunk ----
        if (hok) {
            #pragma unroll
            for (int p = 0; p < 11; ++p) {
                const int r = rb + p;
                if (r < ROWS) {
                    float h1 = 0.f, h2 = 0.f, h3 = 0.f, h4 = 0.f, h5 = 0.f;
                    #pragma unroll
                    for (int k = 0; k < 11; ++k) {
                        const int xx = tid - 5 + k;
                        h1 = fmaf(KW[k], sbuf[p][0][xx], h1);
                        h2 = fmaf(KW[k], sbuf[p][1][xx], h2);
                        h3 = fmaf(KW[k], sbuf[p][2][xx], h3);
                        h4 = fmaf(KW[k], sbuf[p][3][xx], h4);
                        h5 = fmaf(KW[k], sbuf[p][4][xx], h5);
                    }
                    const float mu1s = h1 * h1;
                    const float mu2s = h2 * h2;
                    const float mu12 = h1 * h2;
                    const float num = fmaf(2.f, mu12, 0.0001f) *
                                      fmaf(2.f, h5 - mu12, 0.0009f);
                    const float den = (mu1s + mu2s + 0.0001f) *
                                      ((h3 - mu1s) + (h4 - mu2s) + 0.0009f);
                    acc += __fdividef(num, den);
                }
            }
        }
        __syncthreads();   // protect sbuf before next chunk overwrites
    }

    // ---- block reduction -> one double atomic per CTA; last block finalizes ----
    #pragma unroll
    for (int o = 16; o; o >>= 1) acc += __shfl_xor_sync(0xffffffffu, acc, o);
    if ((tid & 31) == 0) red[tid >> 5] = acc;
    __syncthreads();
    if (tid == 0) {
        const double t = (double)(red[0] + red[1] + red[2] + red[3]);
        atomicAdd(&g_acc, t);
        __threadfence();
        const unsigned int n = atomicAdd(&g_cnt, 1u);
        if (n == NBLK - 1) {
            const double total = atomicAdd(&g_acc, 0.0);   // atomic read
            out[0] = (float)(1.0 - total / 16777216.0);    // 16*1024*1024
            atomicExch((unsigned long long*)&g_acc, 0ull); // reset for next replay
            atomicExch(&g_cnt, 0u);
        }
    }
}

extern "C" void kernel_launch(void* const* d_in, const int* in_sizes, int n_in,
                              void* d_out, int out_size) {
    const float* img1 = (const float*)d_in[0];
    const float* img2 = (const float*)d_in[1];
    float* out = (float*)d_out;

    dim3 grid((IMG_W + W_OUT - 1) / W_OUT, IMG_H / ROWS, 16);  // (9, 16, 16)
    ssim_kernel<<<grid, EW>>>(img1, img2, out);
}

// round 3
// speedup vs baseline: 1.3017x; 1.3017x over previous
#include <cuda_runtime.h>

// SSIM loss, fully fused single kernel — horizontal-first separable blur.
// Horizontal pass reads only 2 raw fields from smem (products built in registers),
// cutting smem crossbar traffic from 240B to 96B per pixel. Vertical pass runs on
// 5 register rings of horizontal sums. Then SSIM + global mean + last-block finalize.

#define IMG_H 1024
#define IMG_W 1024
#define W_OUT 118          // output columns per block
#define EW    128          // extended columns (with 2*5 halo) == blockDim.x
#define ROWS  64           // output rows per block
#define NBLK  (9 * (IMG_H / ROWS) * 16)   // 2304

__device__ double g_acc = 0.0;
__device__ unsigned int g_cnt = 0u;

__global__ __launch_bounds__(EW) void ssim_kernel(const float* __restrict__ img1,
                                                  const float* __restrict__ img2,
                                                  float* __restrict__ out) {
    // Gaussian weights (float32 of the numpy pipeline) as literals -> FFMA immediates.
    const float KW[11] = {
        0.0010283853f, 0.0075987626f, 0.0360007730f, 0.1093606900f,
        0.2130055300f, 0.2660117200f, 0.2130055300f, 0.1093606900f,
        0.0360007730f, 0.0075987626f, 0.0010283853f
    };

    const int tid = threadIdx.x;
    const int bx  = blockIdx.x;   // column strips of W_OUT
    const int by  = blockIdx.y;   // row strips of ROWS
    const int bz  = blockIdx.z;   // batch
    const size_t base = (size_t)bz * (size_t)(IMG_H * IMG_W);

    const int xg  = bx * W_OUT - 5 + tid;          // global column this thread loads
    const bool xok = (xg >= 0) && (xg < IMG_W);
    const int y0  = by * ROWS;
    const float* p1 = img1 + base + xg;
    const float* p2 = img2 + base + xg;

    __shared__ float sraw[11][2][EW];   // one chunk of raw input rows (a, b only)
    __shared__ float red[4];

    // Vertical register rings over the 5 horizontal-sum fields.
    // Input row ri -> slot (ri - (y0-5)) mod 11.
    float v1[11], v2[11], v3[11], v4[11], v5[11];

    const bool hok = (tid >= 5) && (tid < 5 + W_OUT) && (xg < IMG_W);
    float acc = 0.f;

    // ---------- prime: rows y0-5 .. y0+4 -> ring slots 0..9 ----------
    #pragma unroll
    for (int i = 0; i < 10; ++i) {
        const int ri = y0 - 5 + i;
        const bool ok = xok && (ri >= 0);          // ri < IMG_H guaranteed here
        sraw[i][0][tid] = ok ? __ldg(p1 + (size_t)ri * IMG_W) : 0.f;
        sraw[i][1][tid] = ok ? __ldg(p2 + (size_t)ri * IMG_W) : 0.f;
    }
    __syncthreads();
    if (hok) {
        #pragma unroll
        for (int i = 0; i < 10; ++i) {
            float h1 = 0.f, h2 = 0.f, h3 = 0.f, h4 = 0.f, h5 = 0.f;
            #pragma unroll
            for (int k = 0; k < 11; ++k) {
                const float av = sraw[i][0][tid - 5 + k];
                const float bv = sraw[i][1][tid - 5 + k];
                const float ta = KW[k] * av;
                const float tb = KW[k] * bv;
                h1 += ta;  h2 += tb;
                h3 = fmaf(ta, av, h3);
                h4 = fmaf(tb, bv, h4);
                h5 = fmaf(ta, bv, h5);
            }
            v1[i] = h1; v2[i] = h2; v3[i] = h3; v4[i] = h4; v5[i] = h5;
        }
    }
    v1[10] = v2[10] = v3[10] = v4[10] = v5[10] = 0.f;
    __syncthreads();

    // ---------- main loop: chunks of 11 output rows ----------
    #pragma unroll 1
    for (int rb = 0; rb < ROWS; rb += 11) {
        // load phase: raw rows (y0 + rb + p + 5) into sraw[p]
        #pragma unroll
        for (int p = 0; p < 11; ++p) {
            const int r = rb + p;
            if (r < ROWS) {
                const int ri = y0 + r + 5;
                const bool ok = xok && (ri < IMG_H);
                sraw[p][0][tid] = ok ? __ldg(p1 + (size_t)ri * IMG_W) : 0.f;
                sraw[p][1][tid] = ok ? __ldg(p2 + (size_t)ri * IMG_W) : 0.f;
            }
        }
        __syncthreads();

        // compute phase: horizontal sums -> ring, vertical 11-tap + SSIM
        if (hok) {
            #pragma unroll
            for (int p = 0; p < 11; ++p) {
                const int r = rb + p;
                if (r < ROWS) {
                    // horizontal sums for new input row -> slot (p+10)%11
                    float h1 = 0.f, h2 = 0.f, h3 = 0.f, h4 = 0.f, h5 = 0.f;
                    #pragma unroll
                    for (int k = 0; k < 11; ++k) {
                        const float av = sraw[p][0][tid - 5 + k];
                        const float bv = sraw[p][1][tid - 5 + k];
                        const float ta = KW[k] * av;
                        const float tb = KW[k] * bv;
                        h1 += ta;  h2 += tb;
                        h3 = fmaf(ta, av, h3);
                        h4 = fmaf(tb, bv, h4);
                        h5 = fmaf(ta, bv, h5);
                    }
                    const int sl = (p + 10) % 11;      // compile-time
                    v1[sl] = h1; v2[sl] = h2; v3[sl] = h3; v4[sl] = h4; v5[sl] = h5;

                    // vertical 11-tap over ring slots (p+d)%11
                    float m1 = 0.f, m2 = 0.f, m3 = 0.f, m4 = 0.f, m5 = 0.f;
                    #pragma unroll
                    for (int d = 0; d < 11; ++d) {
                        const int s = (p + d) % 11;    // compile-time
                        m1 = fmaf(KW[d], v1[s], m1);
                        m2 = fmaf(KW[d], v2[s], m2);
                        m3 = fmaf(KW[d], v3[s], m3);
                        m4 = fmaf(KW[d], v4[s], m4);
                        m5 = fmaf(KW[d], v5[s], m5);
                    }

                    const float mu1s = m1 * m1;
                    const float mu2s = m2 * m2;
                    const float mu12 = m1 * m2;
                    const float num = fmaf(2.f, mu12, 0.0001f) *
                                      fmaf(2.f, m5 - mu12, 0.0009f);
                    const float den = (mu1s + mu2s + 0.0001f) *
                                      ((m3 - mu1s) + (m4 - mu2s) + 0.0009f);
                    acc += __fdividef(num, den);
                }
            }
        }
        __syncthreads();   // protect sraw before next chunk overwrites
    }

    // ---------- block reduction -> one double atomic; last block finalizes ----------
    #pragma unroll
    for (int o = 16; o; o >>= 1) acc += __shfl_xor_sync(0xffffffffu, acc, o);
    if ((tid & 31) == 0) red[tid >> 5] = acc;
    __syncthreads();
    if (tid == 0) {
        const double t = (double)(red[0] + red[1] + red[2] + red[3]);
        atomicAdd(&g_acc, t);
        __threadfence();
        const unsigned int n = atomicAdd(&g_cnt, 1u);
        if (n == NBLK - 1) {
            const double total = atomicAdd(&g_acc, 0.0);   // atomic read
            out[0] = (float)(1.0 - total / 16777216.0);    // 16*1024*1024
            atomicExch((unsigned long long*)&g_acc, 0ull); // reset for next replay
            atomicExch(&g_cnt, 0u);
        }
    }
}

extern "C" void kernel_launch(void* const* d_in, const int* in_sizes, int n_in,
                              void* d_out, int out_size) {
    const float* img1 = (const float*)d_in[0];
    const float* img2 = (const float*)d_in[1];
    float* out = (float*)d_out;

    dim3 grid((IMG_W + W_OUT - 1) / W_OUT, IMG_H / ROWS, 16);  // (9, 16, 16)
    ssim_kernel<<<grid, EW>>>(img1, img2, out);
}

// round 4
// speedup vs baseline: 1.6407x; 1.2605x over previous
#include <cuda_runtime.h>

// SSIM loss, fully fused — horizontal-first separable blur with f32x2 row-pair packing.
// smem stores raw rows pre-paired as float2 {row r, row r+1}; every horizontal tap is a
// single LDS.64 + packed fma.rn.f32x2 (2 pixels per op). Vertical = scalar FFMA-imm ring.

#define IMG_H 1024
#define IMG_W 1024
#define W_OUT 118
#define EW    128          // blockDim.x
#define ROWS  64
#define NBLK  (9 * (IMG_H / ROWS) * 16)   // 2304

typedef unsigned long long u64;

__device__ double g_acc = 0.0;
__device__ unsigned int g_cnt = 0u;

__device__ __forceinline__ u64 fma2(u64 a, u64 b, u64 c) {
    u64 d; asm("fma.rn.f32x2 %0, %1, %2, %3;" : "=l"(d) : "l"(a), "l"(b), "l"(c)); return d;
}
__device__ __forceinline__ u64 mul2(u64 a, u64 b) {
    u64 d; asm("mul.rn.f32x2 %0, %1, %2;" : "=l"(d) : "l"(a), "l"(b)); return d;
}
__device__ __forceinline__ u64 pack2(float lo, float hi) {
    u64 d; asm("mov.b64 %0, {%1, %2};" : "=l"(d) : "f"(lo), "f"(hi)); return d;
}
__device__ __forceinline__ void unpack2(u64 v, float& lo, float& hi) {
    asm("mov.b64 {%0, %1}, %2;" : "=f"(lo), "=f"(hi) : "l"(v));
}

__global__ __launch_bounds__(EW) void ssim_kernel(const float* __restrict__ img1,
                                                  const float* __restrict__ img2,
                                                  float* __restrict__ out) {
    // float32 of the numpy weight pipeline, as literals.
    const float KW[11] = {
        0.0010283853f, 0.0075987626f, 0.0360007730f, 0.1093606900f,
        0.2130055300f, 0.2660117200f, 0.2130055300f, 0.1093606900f,
        0.0360007730f, 0.0075987626f, 0.0010283853f
    };
    // Packed weights for f32x2 horizontal taps (6 distinct values after CSE).
    u64 kw2[11];
    #pragma unroll
    for (int k = 0; k < 11; ++k) kw2[k] = pack2(KW[k], KW[k]);

    const int tid = threadIdx.x;
    const int bx  = blockIdx.x;
    const int by  = blockIdx.y;
    const int bz  = blockIdx.z;
    const size_t base = (size_t)bz * (size_t)(IMG_H * IMG_W);

    const int xg  = bx * W_OUT - 5 + tid;
    const bool xok = (xg >= 0) && (xg < IMG_W);
    const int y0  = by * ROWS;
    const float* p1 = img1 + base + xg;
    const float* p2 = img2 + base + xg;

    __shared__ float2 spair[6][2][EW];   // [row-pair][field a/b][col], {row r, row r+1}
    __shared__ float red[4];

    // Scalar vertical ring, 12 slots: input row ri -> slot (ri - (y0-5)) mod 12.
    float v1[12], v2[12], v3[12], v4[12], v5[12];

    const bool hok = (tid >= 5) && (tid < 5 + W_OUT) && (xg < IMG_W);
    float acc = 0.f;

    // ---------- prime: input rows y0-5 .. y0+4 (5 pairs) -> ring slots 0..9 ----------
    #pragma unroll
    for (int i = 0; i < 5; ++i) {
        const int r0 = y0 - 5 + 2 * i, r1 = r0 + 1;
        const bool ok0 = xok && (r0 >= 0);
        const bool ok1 = xok && (r1 >= 0);
        spair[i][0][tid] = make_float2(ok0 ? __ldg(p1 + (size_t)r0 * IMG_W) : 0.f,
                                       ok1 ? __ldg(p1 + (size_t)r1 * IMG_W) : 0.f);
        spair[i][1][tid] = make_float2(ok0 ? __ldg(p2 + (size_t)r0 * IMG_W) : 0.f,
                                       ok1 ? __ldg(p2 + (size_t)r1 * IMG_W) : 0.f);
    }
    __syncthreads();
    if (hok) {
        #pragma unroll
        for (int i = 0; i < 5; ++i) {
            u64 h1 = 0, h2 = 0, h3 = 0, h4 = 0, h5 = 0;
            #pragma unroll
            for (int k = 0; k < 11; ++k) {
                const u64 A = *(const u64*)&spair[i][0][tid - 5 + k];
                const u64 B = *(const u64*)&spair[i][1][tid - 5 + k];
                const u64 ta = mul2(kw2[k], A);
                const u64 tb = mul2(kw2[k], B);
                h1 = fma2(kw2[k], A, h1);
                h2 = fma2(kw2[k], B, h2);
                h3 = fma2(ta, A, h3);
                h4 = fma2(tb, B, h4);
                h5 = fma2(ta, B, h5);
            }
            unpack2(h1, v1[2*i], v1[2*i+1]);
            unpack2(h2, v2[2*i], v2[2*i+1]);
            unpack2(h3, v3[2*i], v3[2*i+1]);
            unpack2(h4, v4[2*i], v4[2*i+1]);
            unpack2(h5, v5[2*i], v5[2*i+1]);
        }
    }
    v1[10] = v2[10] = v3[10] = v4[10] = v5[10] = 0.f;
    v1[11] = v2[11] = v3[11] = v4[11] = v5[11] = 0.f;
    __syncthreads();

    // ---------- main loop: chunks of 12 output rows (6 row-pairs) ----------
    #pragma unroll 1
    for (int rb = 0; rb < ROWS; rb += 12) {       // rb ≡ 0 (mod 12)
        // load phase: new input rows rb+5+2j, rb+6+2j -> spair[j]
        #pragma unroll
        for (int j = 0; j < 6; ++j) {
            if (rb + 2 * j < ROWS) {
                const int r0 = y0 + rb + 5 + 2 * j, r1 = r0 + 1;
                const bool ok0 = xok && (r0 < IMG_H);
                const bool ok1 = xok && (r1 < IMG_H);
                spair[j][0][tid] = make_float2(ok0 ? __ldg(p1 + (size_t)r0 * IMG_W) : 0.f,
                                               ok1 ? __ldg(p1 + (size_t)r1 * IMG_W) : 0.f);
                spair[j][1][tid] = make_float2(ok0 ? __ldg(p2 + (size_t)r0 * IMG_W) : 0.f,
                                               ok1 ? __ldg(p2 + (size_t)r1 * IMG_W) : 0.f);
            }
        }
        __syncthreads();

        if (hok) {
            #pragma unroll
            for (int j = 0; j < 6; ++j) {
                if (rb + 2 * j < ROWS) {
                    // packed horizontal for the new input-row pair
                    u64 h1 = 0, h2 = 0, h3 = 0, h4 = 0, h5 = 0;
                    #pragma unroll
                    for (int k = 0; k < 11; ++k) {
                        const u64 A = *(const u64*)&spair[j][0][tid - 5 + k];
                        const u64 B = *(const u64*)&spair[j][1][tid - 5 + k];
                        const u64 ta = mul2(kw2[k], A);
                        const u64 tb = mul2(kw2[k], B);
                        h1 = fma2(kw2[k], A, h1);
                        h2 = fma2(kw2[k], B, h2);
                        h3 = fma2(ta, A, h3);
                        h4 = fma2(tb, B, h4);
                        h5 = fma2(ta, B, h5);
                    }
                    // ring slots for new input rows: (2j+10)%12, (2j+11)%12 (compile-time)
                    const int sA = (2 * j + 10) % 12;
                    const int sB = (2 * j + 11) % 12;
                    unpack2(h1, v1[sA], v1[sB]);
                    unpack2(h2, v2[sA], v2[sB]);
                    unpack2(h3, v3[sA], v3[sB]);
                    unpack2(h4, v4[sA], v4[sB]);
                    unpack2(h5, v5[sA], v5[sB]);

                    // scalar vertical 11-tap + SSIM for output rows rb+2j, rb+2j+1
                    #pragma unroll
                    for (int q = 0; q < 2; ++q) {
                        float m1 = 0.f, m2 = 0.f, m3 = 0.f, m4 = 0.f, m5 = 0.f;
                        #pragma unroll
                        for (int d = 0; d < 11; ++d) {
                            const int s = (2 * j + q + d) % 12;   // compile-time
                            m1 = fmaf(KW[d], v1[s], m1);
                            m2 = fmaf(KW[d], v2[s], m2);
                            m3 = fmaf(KW[d], v3[s], m3);
                            m4 = fmaf(KW[d], v4[s], m4);
                            m5 = fmaf(KW[d], v5[s], m5);
                        }
                        const float mu1s = m1 * m1;
                        const float mu2s = m2 * m2;
                        const float mu12 = m1 * m2;
                        const float num = fmaf(2.f, mu12, 0.0001f) *
                                          fmaf(2.f, m5 - mu12, 0.0009f);
                        const float den = (mu1s + mu2s + 0.0001f) *
                                          ((m3 - mu1s) + (m4 - mu2s) + 0.0009f);
                        acc += __fdividef(num, den);
                    }
                }
            }
        }
        __syncthreads();
    }

    // ---------- reduction + last-block finalize ----------
    #pragma unroll
    for (int o = 16; o; o >>= 1) acc += __shfl_xor_sync(0xffffffffu, acc, o);
    if ((tid & 31) == 0) red[tid >> 5] = acc;
    __syncthreads();
    if (tid == 0) {
        const double t = (double)(red[0] + red[1] + red[2] + red[3]);
        atomicAdd(&g_acc, t);
        __threadfence();
        const unsigned int n = atomicAdd(&g_cnt, 1u);
        if (n == NBLK - 1) {
            const double total = atomicAdd(&g_acc, 0.0);
            out[0] = (float)(1.0 - total / 16777216.0);
            atomicExch((unsigned long long*)&g_acc, 0ull);
            atomicExch(&g_cnt, 0u);
        }
    }
}

extern "C" void kernel_launch(void* const* d_in, const int* in_sizes, int n_in,
                              void* d_out, int out_size) {
    const float* img1 = (const float*)d_in[0];
    const float* img2 = (const float*)d_in[1];
    float* out = (float*)d_out;

    dim3 grid((IMG_W + W_OUT - 1) / W_OUT, IMG_H / ROWS, 16);  // (9, 16, 16)
    ssim_kernel<<<grid, EW>>>(img1, img2, out);
}